// round 15
// baseline (speedup 1.0000x reference)
#include <cuda_runtime.h>
#include <cuda_fp16.h>
#include <math.h>

#define H 192
#define W 192
#define HW (H*W)
#define NCH 24          // BT*C = 8*3
#define CROP 174
#define H0 9
#define W0 9
#define NPIX (CROP*CROP)        // 30276
#define EXT 178                 // CROP + 2*2 halo
#define NPIXE (EXT*EXT)         // 31684
#define NCAND 75
#define SPLIT2 39               // B: 15*39 = 585 blocks (single wave)
#define NSPLITA 236             // A: 3*236 = 708 warp blocks
#define NBT 8
#define NLANES 64
#define NTHR 192
#define IMG_CBLKS (H * 3)                   // 576
#define REF_CHUNKS2 ((NPIX + 191) / 192)    // 158
#define REF_BLKS2 (3 * REF_CHUNKS2)         // 474
#define ROW3W8 (3 * W * 8)

// Image: [y][g][x][8ch]; Ref: [g][p][8ch]; W: [rot][g][pext][8ch]
__device__ __half g_imgT[HW * NCH];
__device__ __half g_refT[NPIX * NCH];
__device__ __half g_W[3 * 3 * NPIXE * 8];
__device__ float  g_partial[NCAND * SPLIT2 * NBT];
__device__ int    g_count;

// ---------------------------------------------------------------------------
// Convert image only: (row, channel-group) blocks.
// ---------------------------------------------------------------------------
__global__ __launch_bounds__(256) void convert_kernel(const float* __restrict__ img) {
    __shared__ __half s[256][10];
    const int b = blockIdx.x;
    const int tid = threadIdx.x;
    if (b == 0 && tid == 0) g_count = 0;

    const int y = b / 3;
    const int g = b - 3 * y;
    if (tid < W) {
        #pragma unroll
        for (int ch = 0; ch < 8; ch++)
            s[tid][ch] = __float2half(img[(g * 8 + ch) * HW + y * W + tid]);
    }
    __syncthreads();
    unsigned int* out32 = (unsigned int*)g_imgT;
    const int base = (y * 3 + g) * 768;
    #pragma unroll
    for (int w = 0; w < 3; w++) {
        const int idx = w * 256 + tid;
        const int x = idx >> 2;
        const int q = idx & 3;
        out32[base + idx] = *(const unsigned int*)&s[x][2 * q];
    }
}

// ---------------------------------------------------------------------------
// Kernel A: blocks [0, 708): bilinear warp for 3 rotations on the 178x178
// extended grid. Blocks [708, 1182): ref-crop conversion (overlapped).
// ---------------------------------------------------------------------------
__global__ __launch_bounds__(NTHR) void warp_ref_kernel(const float* __restrict__ ref) {
    const int b = blockIdx.x;
    const int t = threadIdx.x;

    if (b < 3 * NSPLITA) {
        const int rot = b / NSPLITA;
        const int sA  = b - rot * NSPLITA;
        const int warp = t >> 5;
        const int lane = t & 31;
        const int g = warp % 3;
        const int lane_px = (warp / 3) * 32 + lane;

        const float arot = -(float)(rot - 1) * (float)(M_PI / 180.0);
        const float cr = cosf(arot);
        const float sr = sinf(arot);

        const float SC = 96.0f / 95.5f;
        const float u0 = -86.5f;
        const float v0 = -86.5f;
        const float ax = SC * cr;
        const float bx = -SC * sr;
        const float ay = SC * sr;
        const float by = SC * cr;
        const float cx0e = SC * (cr * u0 - sr * v0) + 95.5f - 2.0f * (ax + bx);
        const float cy0e = SC * (sr * u0 + cr * v0) + 95.5f - 2.0f * (ay + by);

        const int chunkA = (NPIXE + NSPLITA - 1) / NSPLITA;
        const int pb = sA * chunkA;
        const int pe = min(pb + chunkA, NPIXE);

        int p = pb + lane_px;
        int pj;
        float xv, yv;
        {
            const int pi0 = p / EXT;
            pj = p - pi0 * EXT;
            xv = fmaf(ax, (float)pj, fmaf(bx, (float)pi0, cx0e));
            yv = fmaf(ay, (float)pj, fmaf(by, (float)pi0, cy0e));
        }
        const float dxn = ax * (float)NLANES;
        const float dxw = ax * (float)(NLANES - EXT) + bx;
        const float dyn = ay * (float)NLANES;
        const float dyw = ay * (float)(NLANES - EXT) + by;
        const int gW8 = g * W * 8;
        int woff = ((rot * 3 + g) * NPIXE + p) * 8;

        #pragma unroll 2
        for (; p < pe; p += NLANES) {
            const float x0f = floorf(xv);
            const float y0f = floorf(yv);
            const float wx = xv - x0f;
            const float wy = yv - y0f;
            const int x0 = (int)x0f;
            const int y0 = (int)y0f;

            const float wx1 = 1.0f - wx;
            const float wy1 = 1.0f - wy;
            const __half2 wA2 = __float2half2_rn(wx1 * wy1);
            const __half2 wB2 = __float2half2_rn(wx  * wy1);
            const __half2 wC2 = __float2half2_rn(wx1 * wy);
            const __half2 wD2 = __float2half2_rn(wx  * wy);

            const int base = y0 * ROW3W8 + gW8 + x0 * 8;

            const float4 fA = *(const float4*)(g_imgT + base);
            const float4 fB = *(const float4*)(g_imgT + base + 8);
            const float4 fC = *(const float4*)(g_imgT + base + ROW3W8);
            const float4 fD = *(const float4*)(g_imgT + base + ROW3W8 + 8);

            const __half2* hA = (const __half2*)&fA;
            const __half2* hB = (const __half2*)&fB;
            const __half2* hC = (const __half2*)&fC;
            const __half2* hD = (const __half2*)&fD;

            float4 o;
            __half2* ho = (__half2*)&o;
            #pragma unroll
            for (int u = 0; u < 4; u++) {
                __half2 tv = __hmul2(wA2, hA[u]);
                tv = __hfma2(wB2, hB[u], tv);
                tv = __hfma2(wC2, hC[u], tv);
                tv = __hfma2(wD2, hD[u], tv);
                ho[u] = tv;
            }
            *(float4*)(g_W + woff) = o;

            pj += NLANES;
            const bool wrap = (pj >= EXT);
            pj = wrap ? pj - EXT : pj;
            xv += wrap ? dxw : dxn;
            yv += wrap ? dyw : dyn;
            woff += NLANES * 8;
        }
    } else {
        __shared__ __half s[192][10];
        const int bb = b - 3 * NSPLITA;
        const int g = bb / REF_CHUNKS2;
        const int c = bb - g * REF_CHUNKS2;
        const int p0 = c * 192;
        const int p  = p0 + t;
        const bool valid = (p < NPIX);
        const int i = p / CROP;
        const int j = p - i * CROP;
        const int src = (i + H0) * W + (j + W0);
        #pragma unroll
        for (int ch = 0; ch < 8; ch++)
            s[t][ch] = valid ? __float2half(ref[(g * 8 + ch) * HW + src]) : __half(0.0f);
        __syncthreads();
        unsigned int* out32 = (unsigned int*)g_refT;
        #pragma unroll
        for (int w = 0; w < 4; w++) {
            const int idx = w * 192 + t;
            const int px = idx >> 2;
            const int q  = idx & 3;
            if (p0 + px < NPIX)
                out32[(g * NPIX + p0 + px) * 4 + q] = *(const unsigned int*)&s[px][2 * q];
        }
    }
}

// ---------------------------------------------------------------------------
// Kernel B: SAD with 5-way j-shift sharing, half2 accumulation over the
// whole chunk (<=13 iters/lane), single fp32 flush at loop exit.
// ---------------------------------------------------------------------------
__global__ __launch_bounds__(NTHR, 6) void sad_kernel(float* __restrict__ out,
                                                      int out_size) {
    const int pair = blockIdx.x;     // 0..14
    const int s = blockIdx.y;        // 0..SPLIT2-1
    const int t = threadIdx.x;
    const int warp = t >> 5;
    const int lane = t & 31;
    const int g = warp % 3;
    const int lane_px = (warp / 3) * 32 + lane;

    const int i0 = pair / 3;
    const int i2 = pair - 3 * i0;

    __half2 ah[5][4];
    #pragma unroll
    for (int a = 0; a < 5; a++)
        #pragma unroll
        for (int u = 0; u < 4; u++) ah[a][u] = __float2half2_rn(0.0f);

    const int chunk = (NPIX + SPLIT2 - 1) / SPLIT2;
    const int p_begin = s * chunk;
    const int p_end   = min(p_begin + chunk, NPIX);

    int p = p_begin + lane_px;
    int pj;
    int wbase;
    {
        const int pi0 = p / CROP;
        pj = p - pi0 * CROP;
        wbase = ((i2 * 3 + g) * NPIXE + (pi0 + 4 - i0) * EXT + pj) * 8;
    }
    int refoff = (g * NPIX + p) * 8;

    #pragma unroll 2
    for (; p < p_end; p += NLANES) {
        const float4 fR  = *(const float4*)(g_refT + refoff);
        const float4 fW0 = *(const float4*)(g_W + wbase);        // i1 = 4
        const float4 fW1 = *(const float4*)(g_W + wbase + 8);    // i1 = 3
        const float4 fW2 = *(const float4*)(g_W + wbase + 16);   // i1 = 2
        const float4 fW3 = *(const float4*)(g_W + wbase + 24);   // i1 = 1
        const float4 fW4 = *(const float4*)(g_W + wbase + 32);   // i1 = 0
        const __half2* hR = (const __half2*)&fR;
        const float4* fWs[5] = { &fW0, &fW1, &fW2, &fW3, &fW4 };

        #pragma unroll
        for (int k = 0; k < 5; k++) {
            const __half2* hW = (const __half2*)fWs[k];
            const int i1 = 4 - k;
            #pragma unroll
            for (int u = 0; u < 4; u++) {
                ah[i1][u] = __hadd2(ah[i1][u], __habs2(__hsub2(hW[u], hR[u])));
            }
        }

        pj += NLANES;
        const bool wrap = (pj >= CROP);
        pj = wrap ? pj - CROP : pj;
        wbase += wrap ? ((NLANES + (EXT - CROP)) * 8) : (NLANES * 8);
        refoff += NLANES * 8;
    }

    // Single flush to fp32 (deterministic).
    float acc[5][8];
    #pragma unroll
    for (int a = 0; a < 5; a++) {
        #pragma unroll
        for (int u = 0; u < 4; u++) {
            const float2 df = __half22float2(ah[a][u]);
            acc[a][2 * u]     = df.x;
            acc[a][2 * u + 1] = df.y;
        }
    }

    // ---- Deterministic block reduction, one round per i1 ----
    __shared__ float sc[8 * NTHR];
    __shared__ float s2[NBT * 24];
    for (int i1 = 0; i1 < 5; i1++) {
        __syncthreads();
        #pragma unroll
        for (int k = 0; k < 8; k++) sc[k * NTHR + t] = acc[i1][k];
        __syncthreads();
        {
            const int bt = t / 24;
            const int ii = t % 24;
            const int c  = bt * 3 + ii / 8;
            const int gs = c / 8;
            const int k  = c % 8;
            const int m8 = ii % 8;
            float ssum = 0.0f;
            #pragma unroll
            for (int jj = 0; jj < 8; jj++) {
                const int q  = m8 * 8 + jj;
                const int tp = gs * 32 + q + ((q >= 32) ? 64 : 0);
                ssum += sc[k * NTHR + tp];
            }
            s2[bt * 24 + ii] = ssum;
        }
        __syncthreads();
        if (t < NBT) {
            float ssum = 0.0f;
            #pragma unroll
            for (int ii = 0; ii < 24; ii++)
                ssum += s2[t * 24 + ii];
            const int n = i0 * 15 + i1 * 3 + i2;
            g_partial[(n * SPLIT2 + s) * NBT + t] = ssum;
        }
    }

    // ---- Fused finalize ----
    __shared__ int isLast;
    __threadfence();
    __syncthreads();
    if (t == 0) {
        const int old = atomicAdd(&g_count, 1);
        isLast = (old == 15 * SPLIT2 - 1) ? 1 : 0;
    }
    __syncthreads();
    if (isLast) {
        __shared__ float sadSh[NCAND * NBT];
        for (int idx = t; idx < NCAND * NBT; idx += NTHR) {
            const int nn = idx / NBT;
            const int bt = idx - nn * NBT;
            float ssum = 0.0f;
            #pragma unroll
            for (int k = 0; k < SPLIT2; k++)
                ssum += __ldcg(&g_partial[(nn * SPLIT2 + k) * NBT + bt]);
            ssum *= (1.0f / (float)(3 * NPIX));
            sadSh[idx] = ssum;
            out[idx] = ssum;
        }
        __syncthreads();
        if (t < NBT && out_size >= NCAND * NBT + 4 * NBT) {
            const int bt = t;
            float best = sadSh[bt];
            int bn = 0;
            for (int nn = 1; nn < NCAND; nn++) {
                const float v = sadSh[nn * NBT + bt];
                if (v < best) { best = v; bn = nn; }
            }
            const int a0 = bn / 15;
            const int a1 = (bn / 3) % 5;
            const int a2 = bn % 3;
            out[NCAND * NBT + 0 * NBT + bt] = (float)a0;
            out[NCAND * NBT + 1 * NBT + bt] = (float)a1;
            out[NCAND * NBT + 2 * NBT + bt] = (float)a2;
            out[NCAND * NBT + 3 * NBT + bt] = 0.0f;
        }
    }
}

extern "C" void kernel_launch(void* const* d_in, const int* in_sizes, int n_in,
                              void* d_out, int out_size) {
    const float* matrix = (const float*)d_in[0];
    const float* refm   = (const float*)d_in[1];

    convert_kernel<<<IMG_CBLKS, 256>>>(matrix);

    warp_ref_kernel<<<3 * NSPLITA + REF_BLKS2, NTHR>>>(refm);

    dim3 gridB(15, SPLIT2);
    sad_kernel<<<gridB, NTHR>>>((float*)d_out, out_size);
}

// round 16
// speedup vs baseline: 2.2430x; 2.2430x over previous
#include <cuda_runtime.h>
#include <cuda_fp16.h>
#include <math.h>

#define H 192
#define W 192
#define HW (H*W)
#define NCH 24          // BT*C = 8*3
#define CROP 174
#define H0 9
#define W0 9
#define NPIX (CROP*CROP)        // 30276
#define EXT 178                 // CROP + 2*2 halo
#define NPIXE (EXT*EXT)         // 31684
#define NCAND 75
#define SPLIT2 39               // B: 15*39 = 585 blocks (single wave @ occ 4)
#define NSPLITA 236             // A: 3*236 = 708 warp blocks
#define NBT 8
#define NLANES 64
#define NTHR 192
#define IMG_CBLKS (H * 3)                   // 576
#define REF_CHUNKS2 ((NPIX + 191) / 192)    // 158
#define REF_BLKS2 (3 * REF_CHUNKS2)         // 474
#define ROW3W8 (3 * W * 8)

// Image: [y][g][x][8ch]; Ref: [g][p][8ch]; W: [rot][g][pext][8ch]
__device__ __half g_imgT[HW * NCH];
__device__ __half g_refT[NPIX * NCH];
__device__ __half g_W[3 * 3 * NPIXE * 8];
__device__ float  g_partial[NCAND * SPLIT2 * NBT];
__device__ int    g_count;

// ---------------------------------------------------------------------------
// Convert image only: (row, channel-group) blocks.
// ---------------------------------------------------------------------------
__global__ __launch_bounds__(256) void convert_kernel(const float* __restrict__ img) {
    __shared__ __half s[256][10];
    const int b = blockIdx.x;
    const int tid = threadIdx.x;
    if (b == 0 && tid == 0) g_count = 0;

    const int y = b / 3;
    const int g = b - 3 * y;
    if (tid < W) {
        #pragma unroll
        for (int ch = 0; ch < 8; ch++)
            s[tid][ch] = __float2half(img[(g * 8 + ch) * HW + y * W + tid]);
    }
    __syncthreads();
    unsigned int* out32 = (unsigned int*)g_imgT;
    const int base = (y * 3 + g) * 768;
    #pragma unroll
    for (int w = 0; w < 3; w++) {
        const int idx = w * 256 + tid;
        const int x = idx >> 2;
        const int q = idx & 3;
        out32[base + idx] = *(const unsigned int*)&s[x][2 * q];
    }
}

// ---------------------------------------------------------------------------
// Kernel A: blocks [0, 708): bilinear warp for 3 rotations on the 178x178
// extended grid. Blocks [708, 1182): ref-crop conversion (overlapped).
// ---------------------------------------------------------------------------
__global__ __launch_bounds__(NTHR) void warp_ref_kernel(const float* __restrict__ ref) {
    const int b = blockIdx.x;
    const int t = threadIdx.x;

    if (b < 3 * NSPLITA) {
        const int rot = b / NSPLITA;
        const int sA  = b - rot * NSPLITA;
        const int warp = t >> 5;
        const int lane = t & 31;
        const int g = warp % 3;
        const int lane_px = (warp / 3) * 32 + lane;

        const float arot = -(float)(rot - 1) * (float)(M_PI / 180.0);
        const float cr = cosf(arot);
        const float sr = sinf(arot);

        const float SC = 96.0f / 95.5f;
        const float u0 = -86.5f;
        const float v0 = -86.5f;
        const float ax = SC * cr;
        const float bx = -SC * sr;
        const float ay = SC * sr;
        const float by = SC * cr;
        const float cx0e = SC * (cr * u0 - sr * v0) + 95.5f - 2.0f * (ax + bx);
        const float cy0e = SC * (sr * u0 + cr * v0) + 95.5f - 2.0f * (ay + by);

        const int chunkA = (NPIXE + NSPLITA - 1) / NSPLITA;
        const int pb = sA * chunkA;
        const int pe = min(pb + chunkA, NPIXE);

        int p = pb + lane_px;
        int pj;
        float xv, yv;
        {
            const int pi0 = p / EXT;
            pj = p - pi0 * EXT;
            xv = fmaf(ax, (float)pj, fmaf(bx, (float)pi0, cx0e));
            yv = fmaf(ay, (float)pj, fmaf(by, (float)pi0, cy0e));
        }
        const float dxn = ax * (float)NLANES;
        const float dxw = ax * (float)(NLANES - EXT) + bx;
        const float dyn = ay * (float)NLANES;
        const float dyw = ay * (float)(NLANES - EXT) + by;
        const int gW8 = g * W * 8;
        int woff = ((rot * 3 + g) * NPIXE + p) * 8;

        #pragma unroll 2
        for (; p < pe; p += NLANES) {
            const float x0f = floorf(xv);
            const float y0f = floorf(yv);
            const float wx = xv - x0f;
            const float wy = yv - y0f;
            const int x0 = (int)x0f;
            const int y0 = (int)y0f;

            const float wx1 = 1.0f - wx;
            const float wy1 = 1.0f - wy;
            const __half2 wA2 = __float2half2_rn(wx1 * wy1);
            const __half2 wB2 = __float2half2_rn(wx  * wy1);
            const __half2 wC2 = __float2half2_rn(wx1 * wy);
            const __half2 wD2 = __float2half2_rn(wx  * wy);

            const int base = y0 * ROW3W8 + gW8 + x0 * 8;

            const float4 fA = *(const float4*)(g_imgT + base);
            const float4 fB = *(const float4*)(g_imgT + base + 8);
            const float4 fC = *(const float4*)(g_imgT + base + ROW3W8);
            const float4 fD = *(const float4*)(g_imgT + base + ROW3W8 + 8);

            const __half2* hA = (const __half2*)&fA;
            const __half2* hB = (const __half2*)&fB;
            const __half2* hC = (const __half2*)&fC;
            const __half2* hD = (const __half2*)&fD;

            float4 o;
            __half2* ho = (__half2*)&o;
            #pragma unroll
            for (int u = 0; u < 4; u++) {
                __half2 tv = __hmul2(wA2, hA[u]);
                tv = __hfma2(wB2, hB[u], tv);
                tv = __hfma2(wC2, hC[u], tv);
                tv = __hfma2(wD2, hD[u], tv);
                ho[u] = tv;
            }
            *(float4*)(g_W + woff) = o;

            pj += NLANES;
            const bool wrap = (pj >= EXT);
            pj = wrap ? pj - EXT : pj;
            xv += wrap ? dxw : dxn;
            yv += wrap ? dyw : dyn;
            woff += NLANES * 8;
        }
    } else {
        __shared__ __half s[192][10];
        const int bb = b - 3 * NSPLITA;
        const int g = bb / REF_CHUNKS2;
        const int c = bb - g * REF_CHUNKS2;
        const int p0 = c * 192;
        const int p  = p0 + t;
        const bool valid = (p < NPIX);
        const int i = p / CROP;
        const int j = p - i * CROP;
        const int src = (i + H0) * W + (j + W0);
        #pragma unroll
        for (int ch = 0; ch < 8; ch++)
            s[t][ch] = valid ? __float2half(ref[(g * 8 + ch) * HW + src]) : __half(0.0f);
        __syncthreads();
        unsigned int* out32 = (unsigned int*)g_refT;
        #pragma unroll
        for (int w = 0; w < 4; w++) {
            const int idx = w * 192 + t;
            const int px = idx >> 2;
            const int q  = idx & 3;
            if (p0 + px < NPIX)
                out32[(g * NPIX + p0 + px) * 4 + q] = *(const unsigned int*)&s[px][2 * q];
        }
    }
}

// ---------------------------------------------------------------------------
// Kernel B: SAD with 5-way j-shift sharing, half2 accumulation over the
// whole chunk (<=13 iters/lane). Conversion to fp32 happens directly at the
// shared-memory write in the reduction -- NO fp32 staging array, occ 4.
// ---------------------------------------------------------------------------
__global__ __launch_bounds__(NTHR, 4) void sad_kernel(float* __restrict__ out,
                                                      int out_size) {
    const int pair = blockIdx.x;     // 0..14
    const int s = blockIdx.y;        // 0..SPLIT2-1
    const int t = threadIdx.x;
    const int warp = t >> 5;
    const int lane = t & 31;
    const int g = warp % 3;
    const int lane_px = (warp / 3) * 32 + lane;

    const int i0 = pair / 3;
    const int i2 = pair - 3 * i0;

    __half2 ah[5][4];
    #pragma unroll
    for (int a = 0; a < 5; a++)
        #pragma unroll
        for (int u = 0; u < 4; u++) ah[a][u] = __float2half2_rn(0.0f);

    const int chunk = (NPIX + SPLIT2 - 1) / SPLIT2;
    const int p_begin = s * chunk;
    const int p_end   = min(p_begin + chunk, NPIX);

    int p = p_begin + lane_px;
    int pj;
    int wbase;
    {
        const int pi0 = p / CROP;
        pj = p - pi0 * CROP;
        wbase = ((i2 * 3 + g) * NPIXE + (pi0 + 4 - i0) * EXT + pj) * 8;
    }
    int refoff = (g * NPIX + p) * 8;

    #pragma unroll 2
    for (; p < p_end; p += NLANES) {
        const float4 fR  = *(const float4*)(g_refT + refoff);
        const float4 fW0 = *(const float4*)(g_W + wbase);        // i1 = 4
        const float4 fW1 = *(const float4*)(g_W + wbase + 8);    // i1 = 3
        const float4 fW2 = *(const float4*)(g_W + wbase + 16);   // i1 = 2
        const float4 fW3 = *(const float4*)(g_W + wbase + 24);   // i1 = 1
        const float4 fW4 = *(const float4*)(g_W + wbase + 32);   // i1 = 0
        const __half2* hR = (const __half2*)&fR;

        const __half2* hW0 = (const __half2*)&fW0;
        const __half2* hW1 = (const __half2*)&fW1;
        const __half2* hW2 = (const __half2*)&fW2;
        const __half2* hW3 = (const __half2*)&fW3;
        const __half2* hW4 = (const __half2*)&fW4;

        #pragma unroll
        for (int u = 0; u < 4; u++) {
            ah[4][u] = __hadd2(ah[4][u], __habs2(__hsub2(hW0[u], hR[u])));
            ah[3][u] = __hadd2(ah[3][u], __habs2(__hsub2(hW1[u], hR[u])));
            ah[2][u] = __hadd2(ah[2][u], __habs2(__hsub2(hW2[u], hR[u])));
            ah[1][u] = __hadd2(ah[1][u], __habs2(__hsub2(hW3[u], hR[u])));
            ah[0][u] = __hadd2(ah[0][u], __habs2(__hsub2(hW4[u], hR[u])));
        }

        pj += NLANES;
        const bool wrap = (pj >= CROP);
        pj = wrap ? pj - CROP : pj;
        wbase += wrap ? ((NLANES + (EXT - CROP)) * 8) : (NLANES * 8);
        refoff += NLANES * 8;
    }

    // ---- Deterministic block reduction, one round per i1. half2 -> fp32
    //      conversion happens at the smem write (no staging array). ----
    __shared__ float sc[8 * NTHR];
    __shared__ float s2[NBT * 24];
    #pragma unroll
    for (int i1 = 0; i1 < 5; i1++) {
        __syncthreads();
        #pragma unroll
        for (int u = 0; u < 4; u++) {
            const float2 df = __half22float2(ah[i1][u]);
            sc[(2 * u)     * NTHR + t] = df.x;
            sc[(2 * u + 1) * NTHR + t] = df.y;
        }
        __syncthreads();
        {
            const int bt = t / 24;
            const int ii = t % 24;
            const int c  = bt * 3 + ii / 8;
            const int gs = c / 8;
            const int k  = c % 8;
            const int m8 = ii % 8;
            float ssum = 0.0f;
            #pragma unroll
            for (int jj = 0; jj < 8; jj++) {
                const int q  = m8 * 8 + jj;
                const int tp = gs * 32 + q + ((q >= 32) ? 64 : 0);
                ssum += sc[k * NTHR + tp];
            }
            s2[bt * 24 + ii] = ssum;
        }
        __syncthreads();
        if (t < NBT) {
            float ssum = 0.0f;
            #pragma unroll
            for (int ii = 0; ii < 24; ii++)
                ssum += s2[t * 24 + ii];
            const int n = i0 * 15 + i1 * 3 + i2;
            g_partial[(n * SPLIT2 + s) * NBT + t] = ssum;
        }
    }

    // ---- Fused finalize ----
    __shared__ int isLast;
    __threadfence();
    __syncthreads();
    if (t == 0) {
        const int old = atomicAdd(&g_count, 1);
        isLast = (old == 15 * SPLIT2 - 1) ? 1 : 0;
    }
    __syncthreads();
    if (isLast) {
        __shared__ float sadSh[NCAND * NBT];
        for (int idx = t; idx < NCAND * NBT; idx += NTHR) {
            const int nn = idx / NBT;
            const int bt = idx - nn * NBT;
            float ssum = 0.0f;
            #pragma unroll
            for (int k = 0; k < SPLIT2; k++)
                ssum += __ldcg(&g_partial[(nn * SPLIT2 + k) * NBT + bt]);
            ssum *= (1.0f / (float)(3 * NPIX));
            sadSh[idx] = ssum;
            out[idx] = ssum;
        }
        __syncthreads();
        if (t < NBT && out_size >= NCAND * NBT + 4 * NBT) {
            const int bt = t;
            float best = sadSh[bt];
            int bn = 0;
            for (int nn = 1; nn < NCAND; nn++) {
                const float v = sadSh[nn * NBT + bt];
                if (v < best) { best = v; bn = nn; }
            }
            const int a0 = bn / 15;
            const int a1 = (bn / 3) % 5;
            const int a2 = bn % 3;
            out[NCAND * NBT + 0 * NBT + bt] = (float)a0;
            out[NCAND * NBT + 1 * NBT + bt] = (float)a1;
            out[NCAND * NBT + 2 * NBT + bt] = (float)a2;
            out[NCAND * NBT + 3 * NBT + bt] = 0.0f;
        }
    }
}

extern "C" void kernel_launch(void* const* d_in, const int* in_sizes, int n_in,
                              void* d_out, int out_size) {
    const float* matrix = (const float*)d_in[0];
    const float* refm   = (const float*)d_in[1];

    convert_kernel<<<IMG_CBLKS, 256>>>(matrix);

    warp_ref_kernel<<<3 * NSPLITA + REF_BLKS2, NTHR>>>(refm);

    dim3 gridB(15, SPLIT2);
    sad_kernel<<<gridB, NTHR>>>((float*)d_out, out_size);
}